// round 16
// baseline (speedup 1.0000x reference)
#include <cuda_runtime.h>
#include <cstdint>

// DVBundle: intra-CTA TMA-ring persistent kernel (FINAL champion, R4/R15).
//
// w [4096, 8192, 4] f32 = 8192 float4 per neuron row (128KB).
// x [8192,4] -> 8192 float4 (128KB, cached in smem once).
// Output: [v_new (N) | r_new (N) | w_new (N*8192*4)]
//
// Grid = 148 persistent CTAs, 1024 threads. Each CTA loops neurons
// n = bid, bid+148, ... Row streamed as 4 tiles of 32KB via cp.async.bulk
// into a 3-deep smem ring; tiles LDS'd into wv[8] regs (held through the
// update so w is read from DRAM exactly once). Single reduce barrier with
// redundant per-warp broadcast reduce. Per-tile barrier + immediate refill
// keeps the TMA engine streaming through the reduction and store phases.
//
// Six architecture variants (per-tile refill, full-row ring, free-running
// mbars, interleaved R/W, split barriers, evict-first stores) converge at
// 165.4-166.9us in ncu at ~6.15TB/s: the measured 50/50 read/write-mix HBM
// ceiling for the mandatory 1.07GB of traffic (bytes-moved check closes to
// within 5%). This configuration holds the best end-to-end bench and the
// smallest bench-vs-ncu gap of the family.

#define NI        8192
#define THREADS   1024
#define GRID      148
#define TILE_F4   2048               // 32KB tile = 2048 float4
#define TILE_B    32768
#define NBUF      3

#define OFF_X     0
#define OFF_RING  (NI * 16)                      // 131072
#define OFF_RED   (OFF_RING + NBUF * TILE_B)     // 229376
#define OFF_MBAR  (OFF_RED + 33 * 16)            // 229904 (8-aligned)
#define SMEM_B    (OFF_MBAR + NBUF * 8)          // 229928

__device__ __forceinline__ void mbar_wait_parity(uint32_t mbar, uint32_t parity)
{
    uint32_t done;
    asm volatile(
        "{\n\t.reg .pred p;\n\t"
        "mbarrier.try_wait.parity.acquire.cta.shared::cta.b64 p, [%1], %2;\n\t"
        "selp.b32 %0, 1, 0, p;\n\t}"
        : "=r"(done) : "r"(mbar), "r"(parity) : "memory");
    if (!done) {
        asm volatile(
            "{\n\t.reg .pred P1;\n\t"
            "WL_%=:\n\t"
            "mbarrier.try_wait.parity.acquire.cta.shared::cta.b64 P1, [%0], %1, 0x989680;\n\t"
            "@P1 bra.uni WD_%=;\n\t"
            "bra.uni WL_%=;\n\t"
            "WD_%=:\n\t}"
            :: "r"(mbar), "r"(parity) : "memory");
    }
}

__device__ __forceinline__ void issue_tile(int s, int ntiles, int bid,
                                           const float4* __restrict__ w,
                                           uint32_t smem_base, uint32_t mbar_base)
{
    if (s < ntiles) {
        const int      b  = s % 3;
        const uint32_t mb = mbar_base + 8u * b;
        asm volatile("mbarrier.arrive.expect_tx.shared.b64 _, [%0], %1;"
                     :: "r"(mb), "r"((uint32_t)TILE_B) : "memory");
        const void* src = (const void*)(w + (size_t)(bid + (s >> 2) * GRID) * NI
                                          + (size_t)(s & 3) * TILE_F4);
        asm volatile(
            "cp.async.bulk.shared::cluster.global.mbarrier::complete_tx::bytes "
            "[%0], [%1], %2, [%3];"
            :: "r"(smem_base + (uint32_t)OFF_RING + (uint32_t)(b * TILE_B)),
               "l"(src), "r"((uint32_t)TILE_B), "r"(mb) : "memory");
    }
}

__global__ __launch_bounds__(THREADS, 1)
void dvbundle_ring(const float4* __restrict__ w,
                   const float4* __restrict__ x,
                   const float*  __restrict__ v,
                   const float*  __restrict__ r,
                   float*        __restrict__ v_out,
                   float*        __restrict__ r_out,
                   float4*       __restrict__ w_out,
                   int n_neurons)
{
    extern __shared__ char smem[];
    float4* xs   = (float4*)(smem + OFF_X);
    float4* ring = (float4*)(smem + OFF_RING);
    float4* red  = (float4*)(smem + OFF_RED);

    const int tid  = threadIdx.x;
    const int warp = tid >> 5;
    const int lane = tid & 31;
    const int bid  = blockIdx.x;

    const uint32_t smem_base = (uint32_t)__cvta_generic_to_shared(smem);
    const uint32_t mbar_base = smem_base + OFF_MBAR;

    // ---- Prologue: x -> smem, init mbars, prime the ring ----
#pragma unroll
    for (int j = 0; j < 8; ++j)
        xs[tid + j * THREADS] = x[tid + j * THREADS];

    if (tid == 0) {
#pragma unroll
        for (int b = 0; b < NBUF; ++b)
            asm volatile("mbarrier.init.shared.b64 [%0], %1;"
                         :: "r"(mbar_base + 8u * b), "r"(1u) : "memory");
    }
    __syncthreads();

    const int niters = (n_neurons - bid + GRID - 1) / GRID;
    const int ntiles = 4 * niters;

    if (tid == 0) {
        issue_tile(0, ntiles, bid, w, smem_base, mbar_base);
        issue_tile(1, ntiles, bid, w, smem_base, mbar_base);
        issue_tile(2, ntiles, bid, w, smem_base, mbar_base);
    }

    int n = bid;
    for (int it = 0; it < niters; ++it, n += GRID) {
        const float vn = v[n];          // hoisted early, consumed post-reduce
        const float rn = r[n];

        float4 wv[8];
        float ax = 0.f, ay = 0.f, az = 0.f, aw = 0.f;
        const int s0 = 4 * it;

        // ---- Pass 1: 4 tiles, LDS -> regs -> FMA; refill each tile ----
#pragma unroll
        for (int q = 0; q < 4; ++q) {
            const int      s  = s0 + q;
            const int      b  = s % 3;
            const uint32_t ph = (uint32_t)(s / 3) & 1u;
            mbar_wait_parity(mbar_base + 8u * b, ph);

            const float4* wb = ring + b * TILE_F4;
            const float4 w0 = wb[tid];
            const float4 w1 = wb[tid + THREADS];
            const float4 x0 = xs[q * TILE_F4 + tid];
            const float4 x1 = xs[q * TILE_F4 + THREADS + tid];
            wv[2 * q]     = w0;
            wv[2 * q + 1] = w1;
            ax = fmaf(w0.x, x0.x, ax); ax = fmaf(w1.x, x1.x, ax);
            ay = fmaf(w0.y, x0.y, ay); ay = fmaf(w1.y, x1.y, ay);
            az = fmaf(w0.z, x0.z, az); az = fmaf(w1.z, x1.z, az);
            aw = fmaf(w0.w, x0.w, aw); aw = fmaf(w1.w, x1.w, aw);

            __syncthreads();                       // tile b fully consumed
            if (tid == 0)
                issue_tile(s + 3, ntiles, bid, w, smem_base, mbar_base);
        }

        // ---- Reduce: warp shfl -> smem partials -> 1 barrier ->
        //      every warp redundantly reduces all 32 partials ----
#pragma unroll
        for (int o = 16; o > 0; o >>= 1) {
            ax += __shfl_xor_sync(0xffffffffu, ax, o);
            ay += __shfl_xor_sync(0xffffffffu, ay, o);
            az += __shfl_xor_sync(0xffffffffu, az, o);
            aw += __shfl_xor_sync(0xffffffffu, aw, o);
        }
        if (lane == 0) red[warp] = make_float4(ax, ay, az, aw);
        __syncthreads();

        float4 t = red[lane];
        float Ix = t.x, Iy = t.y, Iz = t.z, Iw = t.w;
#pragma unroll
        for (int o = 16; o > 0; o >>= 1) {
            Ix += __shfl_xor_sync(0xffffffffu, Ix, o);
            Iy += __shfl_xor_sync(0xffffffffu, Iy, o);
            Iz += __shfl_xor_sync(0xffffffffu, Iz, o);
            Iw += __shfl_xor_sync(0xffffffffu, Iw, o);
        }

        // ---- Scalar neuron update ----
        const float S    = Ix - Iy + Iz - Iw;
        const float dv   = (S - vn) * 0.05f;            // DT/TAU_V
        const float th   = tanhf(vn);
        const float actd = (vn > 0.f) ? (1.f - th * th) : 0.f;
        const float reg  = rn * actd * dv * 0.02f;      // / TAU_W

        if (tid == 0) {
            v_out[n] = vn + dv;
            r_out[n] = (vn > 0.f) ? th : 0.f;
        }

        // ---- Pass 2: update from regs + smem x, direct STG ----
        float4* wdst = w_out + (size_t)n * NI;
#pragma unroll
        for (int q = 0; q < 4; ++q) {
#pragma unroll
            for (int h = 0; h < 2; ++h) {
                const int    idx = q * TILE_F4 + h * THREADS + tid;
                const float4 xv  = xs[idx];
                const float4 wj  = wv[2 * q + h];
                float4 o;
                o.x = fmaf(reg, fmaf(-wj.x, Ix, 0.5f * xv.x), wj.x);
                o.y = fmaf(reg, fmaf(-wj.y, Iy, 0.5f * xv.y), wj.y);
                o.z = fmaf(reg, fmaf(-wj.z, Iz, 0.5f * xv.z), wj.z);
                o.w = fmaf(reg, fmaf(-wj.w, Iw, 0.5f * xv.w), wj.w);
                wdst[idx] = o;
            }
        }
    }
}

extern "C" void kernel_launch(void* const* d_in, const int* in_sizes, int n_in,
                              void* d_out, int out_size)
{
    const float4* w = (const float4*)d_in[0];
    const float4* x = (const float4*)d_in[1];
    const float*  v = (const float*)d_in[2];
    const float*  r = (const float*)d_in[3];

    const int N = in_sizes[2];                 // 4096 neurons

    float*  out   = (float*)d_out;
    float*  v_out = out;
    float*  r_out = out + N;
    float4* w_out = (float4*)(out + 2 * (size_t)N);

    cudaFuncSetAttribute(dvbundle_ring,
                         cudaFuncAttributeMaxDynamicSharedMemorySize,
                         SMEM_B);

    dvbundle_ring<<<GRID, THREADS, SMEM_B>>>(w, x, v, r, v_out, r_out, w_out, N);
}

// round 17
// speedup vs baseline: 1.0215x; 1.0215x over previous
#include <cuda_runtime.h>
#include <cstdint>

// DVBundle: intra-CTA TMA-ring persistent kernel (champion, 4 barriers/iter).
//
// w [4096, 8192, 4] f32 = 8192 float4 per neuron row (128KB).
// x [8192,4] -> 8192 float4 (128KB, cached in smem once).
// Output: [v_new (N) | r_new (N) | w_new (N*8192*4)]
//
// Grid = 148 persistent CTAs, 1024 threads. Row streamed as 4 tiles of 32KB
// via cp.async.bulk into a 3-deep smem ring; tiles LDS'd into wv[8] regs
// (held through the update so w is read from DRAM exactly once).
// Tiles 0..2: per-tile __syncthreads + immediate refill (s+3).
// Tile 3: consumption proof folded into the reduce __syncthreads, after
// which s0+6 is issued -- one fewer full-CTA convoy per iteration than the
// R4/R15 champion, identical memory behavior and slot-safety ordering.
//
// Measured context: six architecture variants converge at 165.4-166.9us in
// ncu (~6.15TB/s) -- the 50/50 read/write-mix HBM operating point for the
// mandatory 1.07GB. Same-binary reruns show +/-2us in both ncu and bench.

#define NI        8192
#define THREADS   1024
#define GRID      148
#define TILE_F4   2048               // 32KB tile = 2048 float4
#define TILE_B    32768
#define NBUF      3

#define OFF_X     0
#define OFF_RING  (NI * 16)                      // 131072
#define OFF_RED   (OFF_RING + NBUF * TILE_B)     // 229376
#define OFF_MBAR  (OFF_RED + 33 * 16)            // 229904 (8-aligned)
#define SMEM_B    (OFF_MBAR + NBUF * 8)          // 229928

__device__ __forceinline__ void mbar_wait_parity(uint32_t mbar, uint32_t parity)
{
    uint32_t done;
    asm volatile(
        "{\n\t.reg .pred p;\n\t"
        "mbarrier.try_wait.parity.acquire.cta.shared::cta.b64 p, [%1], %2;\n\t"
        "selp.b32 %0, 1, 0, p;\n\t}"
        : "=r"(done) : "r"(mbar), "r"(parity) : "memory");
    if (!done) {
        asm volatile(
            "{\n\t.reg .pred P1;\n\t"
            "WL_%=:\n\t"
            "mbarrier.try_wait.parity.acquire.cta.shared::cta.b64 P1, [%0], %1, 0x989680;\n\t"
            "@P1 bra.uni WD_%=;\n\t"
            "bra.uni WL_%=;\n\t"
            "WD_%=:\n\t}"
            :: "r"(mbar), "r"(parity) : "memory");
    }
}

__device__ __forceinline__ void issue_tile(int s, int ntiles, int bid,
                                           const float4* __restrict__ w,
                                           uint32_t smem_base, uint32_t mbar_base)
{
    if (s < ntiles) {
        const int      b  = s % 3;
        const uint32_t mb = mbar_base + 8u * b;
        asm volatile("mbarrier.arrive.expect_tx.shared.b64 _, [%0], %1;"
                     :: "r"(mb), "r"((uint32_t)TILE_B) : "memory");
        const void* src = (const void*)(w + (size_t)(bid + (s >> 2) * GRID) * NI
                                          + (size_t)(s & 3) * TILE_F4);
        asm volatile(
            "cp.async.bulk.shared::cluster.global.mbarrier::complete_tx::bytes "
            "[%0], [%1], %2, [%3];"
            :: "r"(smem_base + (uint32_t)OFF_RING + (uint32_t)(b * TILE_B)),
               "l"(src), "r"((uint32_t)TILE_B), "r"(mb) : "memory");
    }
}

__global__ __launch_bounds__(THREADS, 1)
void dvbundle_ring4b(const float4* __restrict__ w,
                     const float4* __restrict__ x,
                     const float*  __restrict__ v,
                     const float*  __restrict__ r,
                     float*        __restrict__ v_out,
                     float*        __restrict__ r_out,
                     float4*       __restrict__ w_out,
                     int n_neurons)
{
    extern __shared__ char smem[];
    float4* xs   = (float4*)(smem + OFF_X);
    float4* ring = (float4*)(smem + OFF_RING);
    float4* red  = (float4*)(smem + OFF_RED);

    const int tid  = threadIdx.x;
    const int warp = tid >> 5;
    const int lane = tid & 31;
    const int bid  = blockIdx.x;

    const uint32_t smem_base = (uint32_t)__cvta_generic_to_shared(smem);
    const uint32_t mbar_base = smem_base + OFF_MBAR;

    // ---- Prologue: x -> smem, init mbars, prime the ring ----
#pragma unroll
    for (int j = 0; j < 8; ++j)
        xs[tid + j * THREADS] = x[tid + j * THREADS];

    if (tid == 0) {
#pragma unroll
        for (int b = 0; b < NBUF; ++b)
            asm volatile("mbarrier.init.shared.b64 [%0], %1;"
                         :: "r"(mbar_base + 8u * b), "r"(1u) : "memory");
    }
    __syncthreads();

    const int niters = (n_neurons - bid + GRID - 1) / GRID;
    const int ntiles = 4 * niters;

    if (tid == 0) {
        issue_tile(0, ntiles, bid, w, smem_base, mbar_base);
        issue_tile(1, ntiles, bid, w, smem_base, mbar_base);
        issue_tile(2, ntiles, bid, w, smem_base, mbar_base);
    }

    int n = bid;
    for (int it = 0; it < niters; ++it, n += GRID) {
        const float vn = v[n];          // hoisted early, consumed post-reduce
        const float rn = r[n];

        float4 wv[8];
        float ax = 0.f, ay = 0.f, az = 0.f, aw = 0.f;
        const int s0 = 4 * it;

        // ---- Pass 1: 4 tiles, LDS -> regs -> FMA ----
        // Tiles 0..2: barrier + immediate refill. Tile 3: deferred to reduce.
#pragma unroll
        for (int q = 0; q < 4; ++q) {
            const int      s  = s0 + q;
            const int      b  = s % 3;
            const uint32_t ph = (uint32_t)(s / 3) & 1u;
            mbar_wait_parity(mbar_base + 8u * b, ph);

            const float4* wb = ring + b * TILE_F4;
            const float4 w0 = wb[tid];
            const float4 w1 = wb[tid + THREADS];
            const float4 x0 = xs[q * TILE_F4 + tid];
            const float4 x1 = xs[q * TILE_F4 + THREADS + tid];
            wv[2 * q]     = w0;
            wv[2 * q + 1] = w1;
            ax = fmaf(w0.x, x0.x, ax); ax = fmaf(w1.x, x1.x, ax);
            ay = fmaf(w0.y, x0.y, ay); ay = fmaf(w1.y, x1.y, ay);
            az = fmaf(w0.z, x0.z, az); az = fmaf(w1.z, x1.z, az);
            aw = fmaf(w0.w, x0.w, aw); aw = fmaf(w1.w, x1.w, aw);

            if (q < 3) {
                __syncthreads();                   // tile b fully consumed
                if (tid == 0)
                    issue_tile(s + 3, ntiles, bid, w, smem_base, mbar_base);
            }
        }

        // ---- Reduce: warp shfl -> smem partials -> 1 barrier (also proves
        //      tile 3 consumed) -> refill s0+6 -> redundant per-warp reduce ----
#pragma unroll
        for (int o = 16; o > 0; o >>= 1) {
            ax += __shfl_xor_sync(0xffffffffu, ax, o);
            ay += __shfl_xor_sync(0xffffffffu, ay, o);
            az += __shfl_xor_sync(0xffffffffu, az, o);
            aw += __shfl_xor_sync(0xffffffffu, aw, o);
        }
        if (lane == 0) red[warp] = make_float4(ax, ay, az, aw);
        __syncthreads();

        if (tid == 0)
            issue_tile(s0 + 6, ntiles, bid, w, smem_base, mbar_base);

        float4 t = red[lane];
        float Ix = t.x, Iy = t.y, Iz = t.z, Iw = t.w;
#pragma unroll
        for (int o = 16; o > 0; o >>= 1) {
            Ix += __shfl_xor_sync(0xffffffffu, Ix, o);
            Iy += __shfl_xor_sync(0xffffffffu, Iy, o);
            Iz += __shfl_xor_sync(0xffffffffu, Iz, o);
            Iw += __shfl_xor_sync(0xffffffffu, Iw, o);
        }

        // ---- Scalar neuron update ----
        const float S    = Ix - Iy + Iz - Iw;
        const float dv   = (S - vn) * 0.05f;            // DT/TAU_V
        const float th   = tanhf(vn);
        const float actd = (vn > 0.f) ? (1.f - th * th) : 0.f;
        const float reg  = rn * actd * dv * 0.02f;      // / TAU_W

        if (tid == 0) {
            v_out[n] = vn + dv;
            r_out[n] = (vn > 0.f) ? th : 0.f;
        }

        // ---- Pass 2: update from regs + smem x, direct STG ----
        float4* wdst = w_out + (size_t)n * NI;
#pragma unroll
        for (int q = 0; q < 4; ++q) {
#pragma unroll
            for (int h = 0; h < 2; ++h) {
                const int    idx = q * TILE_F4 + h * THREADS + tid;
                const float4 xv  = xs[idx];
                const float4 wj  = wv[2 * q + h];
                float4 o;
                o.x = fmaf(reg, fmaf(-wj.x, Ix, 0.5f * xv.x), wj.x);
                o.y = fmaf(reg, fmaf(-wj.y, Iy, 0.5f * xv.y), wj.y);
                o.z = fmaf(reg, fmaf(-wj.z, Iz, 0.5f * xv.z), wj.z);
                o.w = fmaf(reg, fmaf(-wj.w, Iw, 0.5f * xv.w), wj.w);
                wdst[idx] = o;
            }
        }
    }
}

extern "C" void kernel_launch(void* const* d_in, const int* in_sizes, int n_in,
                              void* d_out, int out_size)
{
    const float4* w = (const float4*)d_in[0];
    const float4* x = (const float4*)d_in[1];
    const float*  v = (const float*)d_in[2];
    const float*  r = (const float*)d_in[3];

    const int N = in_sizes[2];                 // 4096 neurons

    float*  out   = (float*)d_out;
    float*  v_out = out;
    float*  r_out = out + N;
    float4* w_out = (float4*)(out + 2 * (size_t)N);

    cudaFuncSetAttribute(dvbundle_ring4b,
                         cudaFuncAttributeMaxDynamicSharedMemorySize,
                         SMEM_B);

    dvbundle_ring4b<<<GRID, THREADS, SMEM_B>>>(w, x, v, r, v_out, r_out, w_out, N);
}